// round 6
// baseline (speedup 1.0000x reference)
#include <cuda_runtime.h>
#include <cstdint>

#define B_DIM 16
#define P_DIM 4096
#define T_DIM 1024
#define NTH   1024
#define NBINS 256                    // 4 classes * 8x8 cells
#define PPT (P_DIM / NTH)            // 4 preds per thread

// Zero-initialized scratch; last block resets it each call (graph-replay safe).
__device__ unsigned g_tp;
__device__ unsigned g_done;

// 256-bin inclusive scan using warp shuffles; tid<256 participates.
// s_val[256] in/out; s_wsum[8] scratch. 2 barriers.
__device__ __forceinline__ void scan256(unsigned* s_val, unsigned* s_wsum, int tid) {
    unsigned x = 0;
    const int lane = tid & 31, wid = tid >> 5;
    if (tid < NBINS) {
        x = s_val[tid];
#pragma unroll
        for (int o = 1; o < 32; o <<= 1) {
            unsigned n = __shfl_up_sync(0xFFFFFFFFu, x, o);
            if (lane >= o) x += n;
        }
        if (lane == 31) s_wsum[wid] = x;
    }
    __syncthreads();
    if (tid == 0) {
        unsigned acc = 0;
#pragma unroll
        for (int w = 0; w < 8; w++) { unsigned v = s_wsum[w]; s_wsum[w] = acc; acc += v; }
    }
    __syncthreads();
    if (tid < NBINS) s_val[tid] = x + s_wsum[wid];
    __syncthreads();
}

__global__ void __launch_bounds__(NTH, 1)
loss_kernel(const float* __restrict__ pred, const float* __restrict__ gt,
            float* __restrict__ out)
{
    const int b   = blockIdx.x;
    const int tid = threadIdx.x;

    __shared__ float2         s_xy[P_DIM];        // binned pred coords (32KB)
    __shared__ unsigned short s_pid[P_DIM];       // slot -> original pred id (8KB)
    __shared__ float2         s_txy[T_DIM];       // sorted target coords (8KB)
    __shared__ unsigned char  s_tcls[T_DIM];      // sorted target class (1KB)
    __shared__ unsigned s_phist[NBINS], s_pscan[NBINS], s_pcur[NBINS];
    __shared__ unsigned s_thist[NBINS], s_tcur[NBINS];
    __shared__ unsigned s_wsum[8];
    __shared__ unsigned s_mask[P_DIM / 32];       // per-batch dedup bitmask
    __shared__ int s_last;

    if (tid < NBINS) { s_phist[tid] = 0u; s_thist[tid] = 0u; }
    if (tid < P_DIM / 32) s_mask[tid] = 0u;
    __syncthreads();

    // ---- bin preds by (class, 8x8 cell) ----
    float px[PPT], py[PPT];
    int   pbin[PPT];
#pragma unroll
    for (int i = 0; i < PPT; i++) {
        const int p = tid + i * NTH;
        const float* e = pred + ((size_t)b * P_DIM + p) * 3;
        float c = e[0], x = e[1], y = e[2];
        pbin[i] = (int)c * 64 + (int)(y * 0.125f) * 8 + (int)(x * 0.125f);
        px[i] = x; py[i] = y;
        atomicAdd(&s_phist[pbin[i]], 1u);
    }

    // ---- load + bin this thread's target ----
    float tx, ty; int tcls, tbin;
    {
        const float* e = gt + ((size_t)b * T_DIM + tid) * 3;
        tcls = (int)e[0]; tx = e[1]; ty = e[2];
        tbin = tcls * 64 + (int)(ty * 0.125f) * 8 + (int)(tx * 0.125f);
        atomicAdd(&s_thist[tbin], 1u);
    }
    __syncthreads();

    // ---- scans (inclusive) ----
    if (tid < NBINS) s_pscan[tid] = s_phist[tid];
    __syncthreads();
    scan256(s_pscan, s_wsum, tid);
    if (tid < NBINS) {
        s_pcur[tid] = s_pscan[tid] - s_phist[tid];   // pred bin starts
        s_tcur[tid] = s_thist[tid];                  // reuse as scan input
    }
    __syncthreads();
    scan256(s_tcur, s_wsum, tid);
    if (tid < NBINS) s_tcur[tid] -= s_thist[tid];    // target bin starts
    __syncthreads();

    // ---- scatter preds and targets into sorted order ----
#pragma unroll
    for (int i = 0; i < PPT; i++) {
        unsigned pos = atomicAdd(&s_pcur[pbin[i]], 1u);
        s_xy[pos]  = make_float2(px[i], py[i]);
        s_pid[pos] = (unsigned short)(tid + i * NTH);
    }
    {
        unsigned pos = atomicAdd(&s_tcur[tbin], 1u);
        s_txy[pos]  = make_float2(tx, ty);
        s_tcls[pos] = (unsigned char)tcls;
    }
    __syncthreads();

    // ---- per-target candidate scan (warp-coherent after sort) ----
    {
        float2 q = s_txy[tid];
        const int cls = s_tcls[tid];
        const int cx0 = max(0, (int)((q.x - 5.0f) * 0.125f));
        const int cx1 = min(7, (int)((q.x + 5.0f) * 0.125f));
        const int cy0 = max(0, (int)((q.y - 5.0f) * 0.125f));
        const int cy1 = min(7, (int)((q.y + 5.0f) * 0.125f));

        float bestd2 = __int_as_float(0x7f800000);
        int   bestslot = 0;
        for (int cy = cy0; cy <= cy1; cy++) {
            for (int cx = cx0; cx <= cx1; cx++) {
                const int bin = cls * 64 + cy * 8 + cx;
                const unsigned end = s_pscan[bin];
                for (unsigned s = end - s_phist[bin]; s < end; s++) {
                    float2 c = s_xy[s];                 // broadcast for coherent lanes
                    float dx = c.x - q.x;
                    float dy = c.y - q.y;
                    float d2 = fmaf(dx, dx, dy * dy);
                    if (d2 < bestd2) { bestd2 = d2; bestslot = (int)s; }
                }
            }
        }

        int newbit = 0;
        if (bestd2 <= 25.0f) {
            unsigned p   = s_pid[bestslot];
            unsigned bit = 1u << (p & 31u);
            unsigned old = atomicOr(&s_mask[p >> 5], bit);
            newbit = (old & bit) ? 0 : 1;
        }
        int cnt = __syncthreads_count(newbit);

        if (tid == 0) {
            if (cnt) atomicAdd(&g_tp, (unsigned)cnt);
            __threadfence();
            s_last = (atomicAdd(&g_done, 1u) == B_DIM - 1);
        }
    }
    __syncthreads();
    if (!s_last) return;

    if (tid == 0) {
        __threadfence();
        float tp = (float)atomicAdd(&g_tp, 0u);
        float fp = (float)(B_DIM * P_DIM) - tp;
        float fn = (float)(B_DIM * T_DIM) - tp;
        const float eps = 1e-6f;
        float precision = (tp + eps) / (tp + eps + fp + eps);
        float recall    = (tp + eps) / (tp + fn + eps);
        float f1 = 2.0f * precision * recall / (precision + recall);
        out[0] = 1.0f - f1;
        g_tp = 0u;                                  // reset for next replay
        g_done = 0u;
    }
}

extern "C" void kernel_launch(void* const* d_in, const int* in_sizes, int n_in,
                              void* d_out, int out_size) {
    const float* pred = (const float*)d_in[0];
    const float* gt   = (const float*)d_in[1];
    if (n_in >= 2 && in_sizes[0] == B_DIM * T_DIM * 3) {   // swapped-order guard
        pred = (const float*)d_in[1];
        gt   = (const float*)d_in[0];
    }
    float* out = (float*)d_out;

    loss_kernel<<<B_DIM, NTH>>>(pred, gt, out);
}

// round 9
// speedup vs baseline: 1.4310x; 1.4310x over previous
#include <cuda_runtime.h>
#include <cstdint>

#define B_DIM 16
#define P_DIM 4096
#define T_DIM 1024
#define NT    512
#define QUARTERS 4
#define TPB   (T_DIM / QUARTERS)       // 256 targets per block
#define NBLOCKS (B_DIM * QUARTERS)     // 64
#define NBINS 256                      // 4 classes * 8x8 cells
#define PPT   (P_DIM / NT)             // 8 preds per thread (contiguous)

// Zero-initialized scratch; last block resets it each call (graph-replay safe).
__device__ unsigned g_mask[B_DIM * (P_DIM / 32)];
__device__ unsigned g_tp;
__device__ unsigned g_done;

__global__ void __launch_bounds__(NT, 1)
loss_kernel(const float* __restrict__ pred, const float* __restrict__ gt,
            float* __restrict__ out)
{
    const int b       = blockIdx.x;
    const int quarter = blockIdx.y;
    const int tid     = threadIdx.x;

    __shared__ float2         s_xy[P_DIM];       // binned pred coords (32KB)
    __shared__ unsigned short s_pid[P_DIM];      // slot -> original pred id (8KB)
    __shared__ unsigned s_hist[NBINS];           // bin sizes
    __shared__ unsigned s_scan[NBINS];           // inclusive scan (bin ends)
    __shared__ unsigned s_wsum[8];
    __shared__ int s_last;

    if (tid < NBINS) s_hist[tid] = 0u;
    __syncthreads();

    // ---- phase 1: load 8 contiguous preds (6x LDG.128), bin + rank ----
    float px[PPT], py[PPT];
    int   pbin[PPT], prank[PPT];
    {
        const float4* pb4 = (const float4*)(pred + ((size_t)b * P_DIM + tid * PPT) * 3);
        float4 v0 = pb4[0], v1 = pb4[1], v2 = pb4[2],
               v3 = pb4[3], v4 = pb4[4], v5 = pb4[5];
        float c[PPT];
        c[0]=v0.x; px[0]=v0.y; py[0]=v0.z;
        c[1]=v0.w; px[1]=v1.x; py[1]=v1.y;
        c[2]=v1.z; px[2]=v1.w; py[2]=v2.x;
        c[3]=v2.y; px[3]=v2.z; py[3]=v2.w;
        c[4]=v3.x; px[4]=v3.y; py[4]=v3.z;
        c[5]=v3.w; px[5]=v4.x; py[5]=v4.y;
        c[6]=v4.z; px[6]=v4.w; py[6]=v5.x;
        c[7]=v5.y; px[7]=v5.z; py[7]=v5.w;
#pragma unroll
        for (int i = 0; i < PPT; i++) {
            int cx = min(7, (int)(px[i] * 0.125f));
            int cy = min(7, (int)(py[i] * 0.125f));
            pbin[i]  = (int)c[i] * 64 + cy * 8 + cx;
            prank[i] = (int)atomicAdd(&s_hist[pbin[i]], 1u);  // rank doubles as scatter slot
        }
    }
    __syncthreads();

    // ---- phase 2: 256-bin inclusive scan (shfl, 2 barriers) ----
    {
        unsigned x = 0;
        const int lane = tid & 31, wid = tid >> 5;
        if (tid < NBINS) {
            x = s_hist[tid];
#pragma unroll
            for (int o = 1; o < 32; o <<= 1) {
                unsigned n = __shfl_up_sync(0xFFFFFFFFu, x, o);
                if (lane >= o) x += n;
            }
            if (lane == 31) s_wsum[wid] = x;
        }
        __syncthreads();
        if (tid == 0) {
            unsigned acc = 0;
#pragma unroll
            for (int w = 0; w < 8; w++) { unsigned v = s_wsum[w]; s_wsum[w] = acc; acc += v; }
        }
        __syncthreads();
        if (tid < NBINS) s_scan[tid] = x + s_wsum[wid];
    }
    __syncthreads();

    // ---- phase 3: scatter using precomputed ranks (no second atomic pass) ----
#pragma unroll
    for (int i = 0; i < PPT; i++) {
        unsigned pos = s_scan[pbin[i]] - s_hist[pbin[i]] + (unsigned)prank[i];
        s_xy[pos]  = make_float2(px[i], py[i]);
        s_pid[pos] = (unsigned short)(tid * PPT + i);
    }
    __syncthreads();

    // ---- phase 4: 2 lanes per target scan interleaved candidate slots ----
    int newbit = 0;
    {
        const int t = quarter * TPB + (tid >> 1);   // target index
        const int h = tid & 1;                      // which half of each bin
        const float* e = gt + ((size_t)b * T_DIM + t) * 3;
        const int   tcls = (int)e[0];
        const float tx = e[1], ty = e[2];
        const int cx0 = max(0, (int)((tx - 5.0f) * 0.125f));
        const int cx1 = min(7, (int)((tx + 5.0f) * 0.125f));
        const int cy0 = max(0, (int)((ty - 5.0f) * 0.125f));
        const int cy1 = min(7, (int)((ty + 5.0f) * 0.125f));

        float bestd2 = __int_as_float(0x7f800000);
        int   bestslot = P_DIM;
        for (int cy = cy0; cy <= cy1; cy++) {
            for (int cx = cx0; cx <= cx1; cx++) {
                const int bin = tcls * 64 + cy * 8 + cx;
                const unsigned end = s_scan[bin];
                for (unsigned s = end - s_hist[bin] + h; s < end; s += 2) {
                    float2 q = s_xy[s];
                    float dx = q.x - tx;
                    float dy = q.y - ty;
                    float d2 = fmaf(dx, dx, dy * dy);
                    if (d2 < bestd2) { bestd2 = d2; bestslot = (int)s; }
                }
            }
        }
        // combine the two lanes of this target
        float od2   = __shfl_xor_sync(0xFFFFFFFFu, bestd2, 1);
        int   oslot = __shfl_xor_sync(0xFFFFFFFFu, bestslot, 1);
        if (od2 < bestd2 || (od2 == bestd2 && oslot < bestslot)) {
            bestd2 = od2; bestslot = oslot;
        }

        if (h == 0 && bestd2 <= 25.0f) {
            unsigned p   = s_pid[bestslot];
            unsigned bit = 1u << (p & 31u);
            unsigned old = atomicOr(&g_mask[b * (P_DIM / 32) + (p >> 5)], bit);
            newbit = (old & bit) ? 0 : 1;
        }
    }
    int cnt = __syncthreads_count(newbit);

    if (tid == 0) {
        if (cnt) atomicAdd(&g_tp, (unsigned)cnt);
        __threadfence();
        s_last = (atomicAdd(&g_done, 1u) == NBLOCKS - 1);
    }
    __syncthreads();
    if (!s_last) return;

    // ---- last block: compute f1, reset all scratch for next replay ----
    __threadfence();
    for (int i = tid; i < B_DIM * (P_DIM / 32); i += NT) g_mask[i] = 0u;
    if (tid == 0) {
        float tp = (float)atomicAdd(&g_tp, 0u);
        float fp = (float)(B_DIM * P_DIM) - tp;
        float fn = (float)(B_DIM * T_DIM) - tp;
        const float eps = 1e-6f;
        float precision = (tp + eps) / (tp + eps + fp + eps);
        float recall    = (tp + eps) / (tp + fn + eps);
        float f1 = 2.0f * precision * recall / (precision + recall);
        out[0] = 1.0f - f1;
        g_tp = 0u;
        g_done = 0u;
    }
}

extern "C" void kernel_launch(void* const* d_in, const int* in_sizes, int n_in,
                              void* d_out, int out_size) {
    const float* pred = (const float*)d_in[0];
    const float* gt   = (const float*)d_in[1];
    if (n_in >= 2 && in_sizes[0] == B_DIM * T_DIM * 3) {   // swapped-order guard
        pred = (const float*)d_in[1];
        gt   = (const float*)d_in[0];
    }
    float* out = (float*)d_out;

    dim3 grid(B_DIM, QUARTERS);   // 64 blocks, single wave
    loss_kernel<<<grid, NT>>>(pred, gt, out);
}

// round 12
// speedup vs baseline: 1.7247x; 1.2052x over previous
#include <cuda_runtime.h>
#include <cstdint>

#define B_DIM 16
#define P_DIM 4096
#define T_DIM 1024
#define NT    512
#define EIGHTHS 8
#define TPB   (T_DIM / EIGHTHS)        // 128 targets per block
#define LANES 4                        // NT / TPB lanes per target
#define NBLOCKS (B_DIM * EIGHTHS)      // 128
#define NBINS 256                      // 4 classes * 8x8 cells
#define PPT   (P_DIM / NT)             // 8 preds per thread (contiguous)

// Zero-initialized scratch; last block resets it each call (graph-replay safe).
__device__ unsigned g_mask[B_DIM * (P_DIM / 32)];
__device__ unsigned g_tp;
__device__ unsigned g_done;

__global__ void __launch_bounds__(NT, 1)
loss_kernel(const float* __restrict__ pred, const float* __restrict__ gt,
            float* __restrict__ out)
{
    const int b      = blockIdx.x;
    const int eighth = blockIdx.y;
    const int tid    = threadIdx.x;

    __shared__ float2         s_xy[P_DIM];       // binned pred coords (32KB)
    __shared__ unsigned short s_pid[P_DIM];      // slot -> original pred id (8KB)
    __shared__ unsigned s_hist[NBINS];
    __shared__ unsigned s_scan[NBINS];           // inclusive scan (bin ends)
    __shared__ unsigned s_wsum[8];
    __shared__ int s_last;

    if (tid < NBINS) s_hist[tid] = 0u;
    __syncthreads();

    // ---- phase 1: load 8 contiguous preds (6x LDG.128), bin + rank ----
    float px[PPT], py[PPT];
    int   pbin[PPT], prank[PPT];
    {
        const float4* pb4 = (const float4*)(pred + ((size_t)b * P_DIM + tid * PPT) * 3);
        float4 v0 = pb4[0], v1 = pb4[1], v2 = pb4[2],
               v3 = pb4[3], v4 = pb4[4], v5 = pb4[5];
        float c[PPT];
        c[0]=v0.x; px[0]=v0.y; py[0]=v0.z;
        c[1]=v0.w; px[1]=v1.x; py[1]=v1.y;
        c[2]=v1.z; px[2]=v1.w; py[2]=v2.x;
        c[3]=v2.y; px[3]=v2.z; py[3]=v2.w;
        c[4]=v3.x; px[4]=v3.y; py[4]=v3.z;
        c[5]=v3.w; px[5]=v4.x; py[5]=v4.y;
        c[6]=v4.z; px[6]=v4.w; py[6]=v5.x;
        c[7]=v5.y; px[7]=v5.z; py[7]=v5.w;
#pragma unroll
        for (int i = 0; i < PPT; i++) {
            int cx = min(7, (int)(px[i] * 0.125f));
            int cy = min(7, (int)(py[i] * 0.125f));
            pbin[i]  = (int)c[i] * 64 + cy * 8 + cx;
            prank[i] = (int)atomicAdd(&s_hist[pbin[i]], 1u);
        }
    }
    __syncthreads();

    // ---- phase 2: 256-bin inclusive scan (shfl, 2 barriers) ----
    {
        unsigned x = 0;
        const int lane = tid & 31, wid = tid >> 5;
        if (tid < NBINS) {
            x = s_hist[tid];
#pragma unroll
            for (int o = 1; o < 32; o <<= 1) {
                unsigned n = __shfl_up_sync(0xFFFFFFFFu, x, o);
                if (lane >= o) x += n;
            }
            if (lane == 31) s_wsum[wid] = x;
        }
        __syncthreads();
        if (tid == 0) {
            unsigned acc = 0;
#pragma unroll
            for (int w = 0; w < 8; w++) { unsigned v = s_wsum[w]; s_wsum[w] = acc; acc += v; }
        }
        __syncthreads();
        if (tid < NBINS) s_scan[tid] = x + s_wsum[wid];
    }
    __syncthreads();

    // ---- phase 3: scatter using precomputed ranks ----
#pragma unroll
    for (int i = 0; i < PPT; i++) {
        unsigned pos = s_scan[pbin[i]] - s_hist[pbin[i]] + (unsigned)prank[i];
        s_xy[pos]  = make_float2(px[i], py[i]);
        s_pid[pos] = (unsigned short)(tid * PPT + i);
    }
    __syncthreads();

    // ---- phase 4: 4 lanes per target, row-contiguous candidate ranges ----
    int newbit = 0;
    {
        const int t = eighth * TPB + (tid >> 2);   // target index
        const int h = tid & 3;                     // lane within target
        const float* e = gt + ((size_t)b * T_DIM + t) * 3;
        const int   tcls = (int)e[0];
        const float tx = e[1], ty = e[2];
        const int cx0 = max(0, (int)((tx - 5.0f) * 0.125f));
        const int cx1 = min(7, (int)((tx + 5.0f) * 0.125f));
        const int cy0 = max(0, (int)((ty - 5.0f) * 0.125f));
        const int cy1 = min(7, (int)((ty + 5.0f) * 0.125f));

        float bestd2 = __int_as_float(0x7f800000);
        int   bestslot = P_DIM;
        for (int cy = cy0; cy <= cy1; cy++) {
            // bins cls*64+cy*8+cx0 .. +cx1 are consecutive -> contiguous slots
            const int bin0 = tcls * 64 + cy * 8 + cx0;
            const int bin1 = tcls * 64 + cy * 8 + cx1;
            const unsigned start = s_scan[bin0] - s_hist[bin0];
            const unsigned end   = s_scan[bin1];
            for (unsigned s = start + h; s < end; s += LANES) {
                float2 q = s_xy[s];
                float dx = q.x - tx;
                float dy = q.y - ty;
                float d2 = fmaf(dx, dx, dy * dy);
                if (d2 < bestd2) { bestd2 = d2; bestslot = (int)s; }
            }
        }
        // combine the 4 lanes (butterfly)
#pragma unroll
        for (int o = 1; o < LANES; o <<= 1) {
            float od2   = __shfl_xor_sync(0xFFFFFFFFu, bestd2, o);
            int   oslot = __shfl_xor_sync(0xFFFFFFFFu, bestslot, o);
            if (od2 < bestd2 || (od2 == bestd2 && oslot < bestslot)) {
                bestd2 = od2; bestslot = oslot;
            }
        }

        if (h == 0 && bestd2 <= 25.0f) {
            unsigned p   = s_pid[bestslot];
            unsigned bit = 1u << (p & 31u);
            unsigned old = atomicOr(&g_mask[b * (P_DIM / 32) + (p >> 5)], bit);
            newbit = (old & bit) ? 0 : 1;
        }
    }
    int cnt = __syncthreads_count(newbit);

    if (tid == 0) {
        if (cnt) atomicAdd(&g_tp, (unsigned)cnt);
        __threadfence();
        s_last = (atomicAdd(&g_done, 1u) == NBLOCKS - 1);
    }
    __syncthreads();
    if (!s_last) return;

    // ---- last block: compute f1, reset all scratch for next replay ----
    __threadfence();
    for (int i = tid; i < B_DIM * (P_DIM / 32); i += NT) g_mask[i] = 0u;
    if (tid == 0) {
        float tp = (float)atomicAdd(&g_tp, 0u);
        float fp = (float)(B_DIM * P_DIM) - tp;
        float fn = (float)(B_DIM * T_DIM) - tp;
        const float eps = 1e-6f;
        float precision = (tp + eps) / (tp + eps + fp + eps);
        float recall    = (tp + eps) / (tp + fn + eps);
        float f1 = 2.0f * precision * recall / (precision + recall);
        out[0] = 1.0f - f1;
        g_tp = 0u;
        g_done = 0u;
    }
}

extern "C" void kernel_launch(void* const* d_in, const int* in_sizes, int n_in,
                              void* d_out, int out_size) {
    const float* pred = (const float*)d_in[0];
    const float* gt   = (const float*)d_in[1];
    if (n_in >= 2 && in_sizes[0] == B_DIM * T_DIM * 3) {   // swapped-order guard
        pred = (const float*)d_in[1];
        gt   = (const float*)d_in[0];
    }
    float* out = (float*)d_out;

    dim3 grid(B_DIM, EIGHTHS);   // 128 blocks, single wave
    loss_kernel<<<grid, NT>>>(pred, gt, out);
}